// round 11
// baseline (speedup 1.0000x reference)
#include <cuda_runtime.h>
#include <cuda_fp16.h>
#include <cstdint>

#define INSIZE 512
#define NREFL  64
#define BATCH  8192

// ---------------- device scratch ----------------
__device__ float  g_sigma[INSIZE];
__device__ float  g_gram[2][64][64];       // full Gram of U rows / V rows (natural order)
__device__ float  g_T[2][64][64];          // Tu, Tv (fp32, app-order rows, zero lower)
__device__ __half g_Wu16[64 * 512];        // U rows 0..63 fp16
__device__ __half g_Wv16[64 * 512];        // V rows REVERSED: row a = V[63-a]
__device__ __half g_WupT[512 * 64];        // (Tu*Wu)^T : [n][j]
__device__ __half g_WvpT[512 * 64];        // (Tv*Wv~)^T : [n][a]
__device__ __half g_xh[BATCH * INSIZE];    // x fp16

// ---------------- helpers ----------------
__device__ __forceinline__ uint32_t smem_u32(const void* p) {
    uint32_t a;
    asm("{ .reg .u64 t; cvta.to.shared.u64 t, %1; cvt.u32.u64 %0, t; }" : "=r"(a) : "l"(p));
    return a;
}
__device__ __forceinline__ void cp_async16(uint32_t dst, const void* src) {
    asm volatile("cp.async.cg.shared.global [%0], [%1], 16;" :: "r"(dst), "l"(src) : "memory");
}
#define CP_COMMIT() asm volatile("cp.async.commit_group;" ::: "memory")
#define CP_WAIT1()  asm volatile("cp.async.wait_group 1;" ::: "memory")
#define SWZ64(o) ((o) ^ (((o) >> 3) & 0x30))

__device__ __forceinline__ void ldsm_x4(uint32_t* r, uint32_t addr) {
    asm volatile("ldmatrix.sync.aligned.m8n8.x4.shared.b16 {%0,%1,%2,%3}, [%4];"
                 : "=r"(r[0]), "=r"(r[1]), "=r"(r[2]), "=r"(r[3]) : "r"(addr));
}
__device__ __forceinline__ void mma16816(float* d, const uint32_t* a, const uint32_t* b) {
    asm volatile("mma.sync.aligned.m16n8k16.row.col.f32.f16.f16.f32 "
                 "{%0,%1,%2,%3}, {%4,%5,%6,%7}, {%8,%9}, {%0,%1,%2,%3};"
                 : "+f"(d[0]), "+f"(d[1]), "+f"(d[2]), "+f"(d[3])
                 : "r"(a[0]), "r"(a[1]), "r"(a[2]), "r"(a[3]), "r"(b[0]), "r"(b[1]));
}

// ---------------------------------------------------------------------------
// K1: fused  (a) x -> fp16   (b) full 64x64 Grams of U,V   (c) W fp16 copies
// ---------------------------------------------------------------------------
__global__ __launch_bounds__(256)
void k1_kernel(const float4* __restrict__ x,
               const float* __restrict__ U, const float* __restrict__ V)
{
    const int b = blockIdx.x, t = threadIdx.x;
    if (b < 4096) {
        const int i = b * 256 + t;
        float4 v = x[i];
        __half2* h = (__half2*)g_xh;
        h[i * 2 + 0] = __floats2half2_rn(v.x, v.y);
        h[i * 2 + 1] = __floats2half2_rn(v.z, v.w);
    } else if (b < 4096 + 1024) {
        const int task = (b - 4096) * 8 + (t >> 5);   // 0..8191
        const int lane = t & 31;
        const int mat = task >> 12;
        const int e = task & 4095;
        const int a = e >> 6, c = e & 63;
        const float* M = mat ? V : U;
        const float* ra = M + (size_t)a * 512;
        const float* rb = M + (size_t)c * 512;
        float ss = 0.f;
        #pragma unroll
        for (int j = lane; j < 512; j += 32) ss += ra[j] * rb[j];
        #pragma unroll
        for (int o = 16; o > 0; o >>= 1) ss += __shfl_xor_sync(0xffffffffu, ss, o);
        if (lane == 0) g_gram[mat][a][c] = ss;
    } else {
        const int wb = b - 5120;
        #pragma unroll
        for (int q = 0; q < 2; ++q) {
            const int id = wb * 512 + t + q * 256;   // 0..65535
            const int mat = id >> 15;
            const int rem = id & 32767;
            if (mat == 0) {
                g_Wu16[rem] = __float2half_rn(U[rem]);
            } else {
                const int row = rem >> 9, col = rem & 511;
                g_Wv16[rem] = __float2half_rn(V[(size_t)(63 - row) * 512 + col]);
            }
        }
    }
}

// ---------------------------------------------------------------------------
// tinv: sigma + T = inv(D^-1 + strict_upper(Gram)), U natural / V descending.
// ---------------------------------------------------------------------------
__global__ __launch_bounds__(1024)
void tinv_kernel(const float* __restrict__ p)
{
    __shared__ float Gs[2][64][64];
    const int t = threadIdx.x;
    if (t < INSIZE) {
        float s = 1.0f / (1.0f + expf(-p[t]));
        g_sigma[t] = 0.1f + 0.9f * s;
    }
    for (int i = t; i < 2 * 4096; i += 1024)
        ((float*)Gs)[i] = ((const float*)g_gram)[i];
    __syncthreads();

    const int w = t >> 5, lane = t & 31;
    #pragma unroll 1
    for (int rnd = 0; rnd < 4; ++rnd) {
        const int task = w + 32 * rnd;         // 0..127
        const int mat = task >> 6, c = task & 63;
        auto Lv = [&](int a, int m) -> float {
            if (mat == 0) return (a == m) ? Gs[0][a][a] * 0.5f : Gs[0][a][m];
            return (a == m) ? Gs[1][63 - a][63 - a] * 0.5f : Gs[1][63 - a][63 - m];
        };
        float t0 = 0.f, t1 = 0.f;
        {
            const float inv = 1.0f / Lv(c, c);
            if (lane == c) t0 = inv;
            if (lane + 32 == c) t1 = inv;
        }
        for (int a = c - 1; a >= 0; --a) {
            float s = 0.f;
            if (lane > a && lane <= c)            s += Lv(a, lane) * t0;
            if (lane + 32 > a && lane + 32 <= c)  s += Lv(a, lane + 32) * t1;
            #pragma unroll
            for (int o = 16; o > 0; o >>= 1) s += __shfl_xor_sync(0xffffffffu, s, o);
            const float ta = -s / Lv(a, a);
            if (lane == a) t0 = ta;
            if (lane + 32 == a) t1 = ta;
        }
        g_T[mat][lane][c]      = t0;
        g_T[mat][lane + 32][c] = t1;
    }
}

// ---------------------------------------------------------------------------
// applyT: W' = T * W (app-order), stored transposed fp16 [n][64].
// ---------------------------------------------------------------------------
__global__ __launch_bounds__(256)
void applyT_kernel(const float* __restrict__ U, const float* __restrict__ V)
{
    __shared__ float Ts[64 * 64];
    const int b = blockIdx.x, t = threadIdx.x;
    const int mat = b >> 3, n0 = (b & 7) * 64;
    for (int i = t; i < 4096; i += 256) Ts[i] = (&g_T[mat][0][0])[i];
    __syncthreads();

    const int n = n0 + (t & 63);
    const int jg = t >> 6;
    float s[16];
    #pragma unroll
    for (int j = 0; j < 16; ++j) s[j] = 0.f;
    #pragma unroll 4
    for (int k = 0; k < 64; ++k) {
        const float w = mat ? __ldg(&V[(size_t)(63 - k) * 512 + n])
                            : __ldg(&U[(size_t)k * 512 + n]);
        #pragma unroll
        for (int j = 0; j < 16; ++j)
            s[j] += Ts[(jg * 16 + j) * 64 + k] * w;
    }
    __half* dst = mat ? g_WvpT : g_WupT;
    #pragma unroll
    for (int j = 0; j < 16; ++j)
        dst[(size_t)n * 64 + jg * 16 + j] = __float2half_rn(s[j]);
}

// ---------------------------------------------------------------------------
// mega: per 64-row tile, fully fused WY-64 application.
//  S1: P = x16 * Wu16^T      S2: Z = (x - P*Wu'^T)*sigma
//  S3: Q = Z16 * Wv16~^T     S4: out = Z - Q*Wv'^T + bias
// smem: Z 65536 | P 8192 | sig 2048 | staging 3x8192  = 100352 bytes
// ---------------------------------------------------------------------------
#define OFF_Z   0
#define OFF_P   65536
#define OFF_SIG 73728
#define OFF_STG 75776
#define MEGA_SMEM 100352

__global__ __launch_bounds__(256)
void mega_kernel(const float* __restrict__ x, float* __restrict__ out,
                 const float* __restrict__ bias)
{
    extern __shared__ __align__(1024) char sm[];
    const uint32_t sb = smem_u32(sm);
    const int t = threadIdx.x, lane = t & 31, wid = t >> 5;
    const int wm = wid & 3, wn = wid >> 2;    // 4 x 2 warp grid over [64 x 64]
    const int m0 = blockIdx.x * 64;
    float* sig = (float*)(sm + OFF_SIG);

    for (int i = t; i < 512; i += 256) sig[i] = g_sigma[i];

    const int arow = wm * 16 + (lane & 15);
    const int r0l  = wm * 16 + (lane >> 2);

    auto load_ab64 = [&](int slot, int ks, const __half* Asrc, const __half* Bsrc) {
        const int row = t >> 2, c4 = t & 3;
        const uint32_t so = SWZ64((uint32_t)(row * 64 + c4 * 16));
        cp_async16(sb + OFF_STG + slot * 8192 + so, Asrc + (size_t)row * 512 + ks * 32 + c4 * 8);
        cp_async16(sb + OFF_STG + slot * 8192 + 4096 + so, Bsrc + (size_t)row * 512 + ks * 32 + c4 * 8);
    };
    auto load_b64 = [&](int slot, int ks, const __half* Bsrc) {
        const int row = t >> 2, c4 = t & 3;
        cp_async16(sb + OFF_STG + slot * 8192 + SWZ64((uint32_t)(row * 64 + c4 * 16)),
                   Bsrc + (size_t)row * 512 + ks * 32 + c4 * 8);
    };
    auto load_wp = [&](int slot, int nc, const __half* Wp) {
        #pragma unroll
        for (int i = 0; i < 2; ++i) {
            const int idx = t + i * 256;
            const int row = idx >> 3, c8 = idx & 7;
            cp_async16(sb + OFF_STG + slot * 8192 + (c8 >> 2) * 4096
                           + SWZ64((uint32_t)(row * 64 + (c8 & 3) * 16)),
                       Wp + (size_t)(nc * 64 + row) * 64 + c8 * 8);
        }
    };
    auto bfrag_addr = [&](uint32_t base, int fp, int kf) -> uint32_t {
        const int brow = wn * 32 + fp * 16 + ((lane >> 4) << 3) + (lane & 7);
        return base + SWZ64((uint32_t)(brow * 64 + (kf * 2 + ((lane >> 3) & 1)) * 16));
    };
    auto afrag_addr = [&](uint32_t base, int kf) -> uint32_t {
        return base + SWZ64((uint32_t)(arow * 64 + (kf * 2 + (lane >> 4)) * 16));
    };
    auto store_p16 = [&](float acc[4][4]) {
        #pragma unroll
        for (int fn = 0; fn < 4; ++fn) {
            const int colin = fn * 8 + (lane & 3) * 2;
            *(__half2*)(sm + OFF_P + wn * 4096 + SWZ64((uint32_t)(r0l * 64 + colin * 2)))
                = __floats2half2_rn(acc[fn][0], acc[fn][1]);
            *(__half2*)(sm + OFF_P + wn * 4096 + SWZ64((uint32_t)((r0l + 8) * 64 + colin * 2)))
                = __floats2half2_rn(acc[fn][2], acc[fn][3]);
        }
    };

    // ================= S1: P = x16 * Wu16^T =================
    float acc[4][4];
    #pragma unroll
    for (int fn = 0; fn < 4; ++fn)
        #pragma unroll
        for (int j = 0; j < 4; ++j) acc[fn][j] = 0.f;

    const __half* Ax = g_xh + (size_t)m0 * 512;
    load_ab64(0, 0, Ax, g_Wu16); CP_COMMIT();
    load_ab64(1, 1, Ax, g_Wu16); CP_COMMIT();
    #pragma unroll 1
    for (int ks = 0; ks < 16; ++ks) {
        CP_WAIT1();
        __syncthreads();
        if (ks + 2 < 16) load_ab64((ks + 2) % 3, ks + 2, Ax, g_Wu16);
        CP_COMMIT();
        const uint32_t base = sb + OFF_STG + (ks % 3) * 8192;
        #pragma unroll
        for (int kf = 0; kf < 2; ++kf) {
            uint32_t a[4], bfr[2][4];
            ldsm_x4(a, afrag_addr(base, kf));
            #pragma unroll
            for (int fp = 0; fp < 2; ++fp) ldsm_x4(bfr[fp], bfrag_addr(base + 4096, fp, kf));
            #pragma unroll
            for (int fn = 0; fn < 4; ++fn) mma16816(acc[fn], a, &bfr[fn >> 1][(fn & 1) * 2]);
        }
    }
    store_p16(acc);
    __syncthreads();

    uint32_t a2[2][2][4];
    #pragma unroll
    for (int kc = 0; kc < 2; ++kc)
        #pragma unroll
        for (int kf = 0; kf < 2; ++kf)
            ldsm_x4(a2[kc][kf], afrag_addr(sb + OFF_P + kc * 4096, kf));

    // ================= S2: Z = (x - P*Wu'^T) * sigma =================
    load_wp(0, 0, g_WupT); CP_COMMIT();
    load_wp(1, 1, g_WupT); CP_COMMIT();
    #pragma unroll 1
    for (int nc = 0; nc < 8; ++nc) {
        CP_WAIT1();
        __syncthreads();
        if (nc + 2 < 8) load_wp((nc + 2) % 3, nc + 2, g_WupT);
        CP_COMMIT();
        float a4[4][4];
        #pragma unroll
        for (int fn = 0; fn < 4; ++fn)
            #pragma unroll
            for (int j = 0; j < 4; ++j) a4[fn][j] = 0.f;
        const uint32_t base = sb + OFF_STG + (nc % 3) * 8192;
        #pragma unroll
        for (int kc = 0; kc < 2; ++kc)
            #pragma unroll
            for (int kf = 0; kf < 2; ++kf) {
                uint32_t bfr[2][4];
                #pragma unroll
                for (int fp = 0; fp < 2; ++fp)
                    ldsm_x4(bfr[fp], bfrag_addr(base + kc * 4096, fp, kf));
                #pragma unroll
                for (int fn = 0; fn < 4; ++fn)
                    mma16816(a4[fn], a2[kc][kf], &bfr[fn >> 1][(fn & 1) * 2]);
            }
        const int gr0 = m0 + r0l;
        #pragma unroll
        for (int fn = 0; fn < 4; ++fn) {
            const int n = nc * 64 + wn * 32 + fn * 8 + (lane & 3) * 2;
            float2 xv0 = __ldg((const float2*)(x + (size_t)gr0 * 512 + n));
            float2 xv1 = __ldg((const float2*)(x + (size_t)(gr0 + 8) * 512 + n));
            const float s0 = sig[n], s1 = sig[n + 1];
            const int chunk = n >> 5, cin = n & 31;
            *(__half2*)(sm + OFF_Z + chunk * 4096 + SWZ64((uint32_t)(r0l * 64 + cin * 2)))
                = __floats2half2_rn((xv0.x - a4[fn][0]) * s0, (xv0.y - a4[fn][1]) * s1);
            *(__half2*)(sm + OFF_Z + chunk * 4096 + SWZ64((uint32_t)((r0l + 8) * 64 + cin * 2)))
                = __floats2half2_rn((xv1.x - a4[fn][2]) * s0, (xv1.y - a4[fn][3]) * s1);
        }
    }
    __syncthreads();

    // ================= S3: Q = Z16 * Wv16~^T =================
    #pragma unroll
    for (int fn = 0; fn < 4; ++fn)
        #pragma unroll
        for (int j = 0; j < 4; ++j) acc[fn][j] = 0.f;
    load_b64(0, 0, g_Wv16); CP_COMMIT();
    load_b64(1, 1, g_Wv16); CP_COMMIT();
    #pragma unroll 1
    for (int ks = 0; ks < 16; ++ks) {
        CP_WAIT1();
        __syncthreads();
        if (ks + 2 < 16) load_b64((ks + 2) % 3, ks + 2, g_Wv16);
        CP_COMMIT();
        const uint32_t bbase = sb + OFF_STG + (ks % 3) * 8192;
        const uint32_t abase = sb + OFF_Z + ks * 4096;
        #pragma unroll
        for (int kf = 0; kf < 2; ++kf) {
            uint32_t a[4], bfr[2][4];
            ldsm_x4(a, afrag_addr(abase, kf));
            #pragma unroll
            for (int fp = 0; fp < 2; ++fp) ldsm_x4(bfr[fp], bfrag_addr(bbase, fp, kf));
            #pragma unroll
            for (int fn = 0; fn < 4; ++fn) mma16816(acc[fn], a, &bfr[fn >> 1][(fn & 1) * 2]);
        }
    }
    __syncthreads();
    store_p16(acc);            // Q16 into OFF_P
    __syncthreads();

    #pragma unroll
    for (int kc = 0; kc < 2; ++kc)
        #pragma unroll
        for (int kf = 0; kf < 2; ++kf)
            ldsm_x4(a2[kc][kf], afrag_addr(sb + OFF_P + kc * 4096, kf));

    // ================= S4: out = Z - Q*Wv'^T + bias =================
    load_wp(0, 0, g_WvpT); CP_COMMIT();
    load_wp(1, 1, g_WvpT); CP_COMMIT();
    #pragma unroll 1
    for (int nc = 0; nc < 8; ++nc) {
        CP_WAIT1();
        __syncthreads();
        if (nc + 2 < 8) load_wp((nc + 2) % 3, nc + 2, g_WvpT);
        CP_COMMIT();
        float a4[4][4];
        #pragma unroll
        for (int fn = 0; fn < 4; ++fn)
            #pragma unroll
            for (int j = 0; j < 4; ++j) a4[fn][j] = 0.f;
        const uint32_t base = sb + OFF_STG + (nc % 3) * 8192;
        #pragma unroll
        for (int kc = 0; kc < 2; ++kc)
            #pragma unroll
            for (int kf = 0; kf < 2; ++kf) {
                uint32_t bfr[2][4];
                #pragma unroll
                for (int fp = 0; fp < 2; ++fp)
                    ldsm_x4(bfr[fp], bfrag_addr(base + kc * 4096, fp, kf));
                #pragma unroll
                for (int fn = 0; fn < 4; ++fn)
                    mma16816(a4[fn], a2[kc][kf], &bfr[fn >> 1][(fn & 1) * 2]);
            }
        const int gr0 = m0 + r0l;
        #pragma unroll
        for (int fn = 0; fn < 4; ++fn) {
            const int n = nc * 64 + wn * 32 + fn * 8 + (lane & 3) * 2;
            const int chunk = n >> 5, cin = n & 31;
            float2 z0 = __half22float2(*(__half2*)(sm + OFF_Z + chunk * 4096
                                       + SWZ64((uint32_t)(r0l * 64 + cin * 2))));
            float2 z1 = __half22float2(*(__half2*)(sm + OFF_Z + chunk * 4096
                                       + SWZ64((uint32_t)((r0l + 8) * 64 + cin * 2))));
            const float2 bi = __ldg((const float2*)(bias + n));
            float2 o0, o1;
            o0.x = z0.x - a4[fn][0] + bi.x; o0.y = z0.y - a4[fn][1] + bi.y;
            o1.x = z1.x - a4[fn][2] + bi.x; o1.y = z1.y - a4[fn][3] + bi.y;
            *(float2*)(out + (size_t)gr0 * 512 + n)       = o0;
            *(float2*)(out + (size_t)(gr0 + 8) * 512 + n) = o1;
        }
    }
}

// ---------------------------------------------------------------------------
extern "C" void kernel_launch(void* const* d_in, const int* in_sizes, int n_in,
                              void* d_out, int out_size)
{
    (void)in_sizes; (void)n_in; (void)out_size;
    const float* x    = (const float*)d_in[0];
    const float* p    = (const float*)d_in[1];
    const float* U    = (const float*)d_in[2];
    const float* V    = (const float*)d_in[3];
    const float* bias = (const float*)d_in[4];

    cudaFuncSetAttribute(mega_kernel, cudaFuncAttributeMaxDynamicSharedMemorySize,
                         MEGA_SMEM);

    k1_kernel<<<5248, 256>>>((const float4*)x, U, V);
    tinv_kernel<<<1, 1024>>>(p);
    applyT_kernel<<<16, 256>>>(U, V);
    mega_kernel<<<BATCH / 64, 256, MEGA_SMEM>>>(x, (float*)d_out, bias);
}

// round 12
// speedup vs baseline: 1.7958x; 1.7958x over previous
#include <cuda_runtime.h>
#include <cuda_fp16.h>
#include <cstdint>

#define INSIZE 512
#define NREFL  64
#define BATCH  8192

// ---------------- device scratch ----------------
__device__ float  g_sigma[INSIZE];
__device__ float  g_gram[2][64][64];
__device__ float  g_T[2][64][64];       // Tu, Tv (app-order)
__device__ float  g_C1[64 * 512];       // (Tu*Wu)*Sigma, row-major [a][j]
__device__ float  g_Wvp[64 * 512];      // Tv*Wv~, row-major [b][j]
__device__ float  g_C2[64 * 64];        // C1 * Wv~^T
__device__ float  g_E[512 * 64];        // Sigma*Wv~^T - Wu^T*C2, [i][b]
__device__ __half g_MT[512 * 512];      // M^T fp16: [n][k]
__device__ __half g_xh[BATCH * INSIZE];

// ---------------- helpers ----------------
__device__ __forceinline__ uint32_t smem_u32(const void* p) {
    uint32_t a;
    asm("{ .reg .u64 t; cvta.to.shared.u64 t, %1; cvt.u32.u64 %0, t; }" : "=r"(a) : "l"(p));
    return a;
}
__device__ __forceinline__ void cp_async16(uint32_t dst, const void* src) {
    asm volatile("cp.async.cg.shared.global [%0], [%1], 16;" :: "r"(dst), "l"(src) : "memory");
}
#define CP_COMMIT() asm volatile("cp.async.commit_group;" ::: "memory")
#define CP_WAIT1()  asm volatile("cp.async.wait_group 1;" ::: "memory")
#define SWZ64(o) ((o) ^ (((o) >> 3) & 0x30))

__device__ __forceinline__ void ldsm_x4(uint32_t* r, uint32_t addr) {
    asm volatile("ldmatrix.sync.aligned.m8n8.x4.shared.b16 {%0,%1,%2,%3}, [%4];"
                 : "=r"(r[0]), "=r"(r[1]), "=r"(r[2]), "=r"(r[3]) : "r"(addr));
}
__device__ __forceinline__ void mma16816(float* d, const uint32_t* a, const uint32_t* b) {
    asm volatile("mma.sync.aligned.m16n8k16.row.col.f32.f16.f16.f32 "
                 "{%0,%1,%2,%3}, {%4,%5,%6,%7}, {%8,%9}, {%0,%1,%2,%3};"
                 : "+f"(d[0]), "+f"(d[1]), "+f"(d[2]), "+f"(d[3])
                 : "r"(a[0]), "r"(a[1]), "r"(a[2]), "r"(a[3]), "r"(b[0]), "r"(b[1]));
}

// ---------------------------------------------------------------------------
// K1: (a) x -> fp16   (b) full 64x64 Grams of U,V
// ---------------------------------------------------------------------------
__global__ __launch_bounds__(256)
void k1_kernel(const float4* __restrict__ x,
               const float* __restrict__ U, const float* __restrict__ V)
{
    const int b = blockIdx.x, t = threadIdx.x;
    if (b < 4096) {
        const int i = b * 256 + t;
        float4 v = x[i];
        __half2* h = (__half2*)g_xh;
        h[i * 2 + 0] = __floats2half2_rn(v.x, v.y);
        h[i * 2 + 1] = __floats2half2_rn(v.z, v.w);
    } else {
        const int task = (b - 4096) * 8 + (t >> 5);   // 0..8191
        const int lane = t & 31;
        const int mat = task >> 12;
        const int e = task & 4095;
        const int a = e >> 6, c = e & 63;
        const float* M = mat ? V : U;
        const float* ra = M + (size_t)a * 512;
        const float* rb = M + (size_t)c * 512;
        float ss = 0.f;
        #pragma unroll
        for (int j = lane; j < 512; j += 32) ss += ra[j] * rb[j];
        #pragma unroll
        for (int o = 16; o > 0; o >>= 1) ss += __shfl_xor_sync(0xffffffffu, ss, o);
        if (lane == 0) g_gram[mat][a][c] = ss;
    }
}

// ---------------------------------------------------------------------------
// tinv: sigma + T = inv(D^-1 + strict_upper(Gram)). 4 independent blocks.
// ---------------------------------------------------------------------------
__global__ __launch_bounds__(1024)
void tinv_kernel(const float* __restrict__ p)
{
    __shared__ float Gs[2][64][64];
    const int t = threadIdx.x;
    if (blockIdx.x == 0 && t < INSIZE) {
        float s = 1.0f / (1.0f + expf(-p[t]));
        g_sigma[t] = 0.1f + 0.9f * s;
    }
    for (int i = t; i < 2 * 4096; i += 1024)
        ((float*)Gs)[i] = ((const float*)g_gram)[i];
    __syncthreads();

    const int w = t >> 5, lane = t & 31;
    const int task = w + 32 * blockIdx.x;      // 0..127
    const int mat = task >> 6, c = task & 63;
    auto Lv = [&](int a, int m) -> float {
        if (mat == 0) return (a == m) ? Gs[0][a][a] * 0.5f : Gs[0][a][m];
        return (a == m) ? Gs[1][63 - a][63 - a] * 0.5f : Gs[1][63 - a][63 - m];
    };
    float t0 = 0.f, t1 = 0.f;
    {
        const float inv = 1.0f / Lv(c, c);
        if (lane == c) t0 = inv;
        if (lane + 32 == c) t1 = inv;
    }
    for (int a = c - 1; a >= 0; --a) {
        float s = 0.f;
        if (lane > a && lane <= c)            s += Lv(a, lane) * t0;
        if (lane + 32 > a && lane + 32 <= c)  s += Lv(a, lane + 32) * t1;
        #pragma unroll
        for (int o = 16; o > 0; o >>= 1) s += __shfl_xor_sync(0xffffffffu, s, o);
        const float ta = -s / Lv(a, a);
        if (lane == a) t0 = ta;
        if (lane + 32 == a) t1 = ta;
    }
    g_T[mat][lane][c]      = t0;
    g_T[mat][lane + 32][c] = t1;
}

// ---------------------------------------------------------------------------
// applyT: mat 0 -> g_C1 = (Tu*Wu)*Sigma; mat 1 -> g_Wvp = Tv*Wv~. fp32 [a][n].
// ---------------------------------------------------------------------------
__global__ __launch_bounds__(256)
void applyT_kernel(const float* __restrict__ U, const float* __restrict__ V)
{
    __shared__ float Ts[64 * 64];
    const int b = blockIdx.x, t = threadIdx.x;
    const int mat = b >> 3, n0 = (b & 7) * 64;
    for (int i = t; i < 4096; i += 256) Ts[i] = (&g_T[mat][0][0])[i];
    __syncthreads();

    const int n = n0 + (t & 63);
    const int jg = t >> 6;
    float s[16];
    #pragma unroll
    for (int j = 0; j < 16; ++j) s[j] = 0.f;
    #pragma unroll 4
    for (int k = 0; k < 64; ++k) {
        const float w = mat ? __ldg(&V[(size_t)(63 - k) * 512 + n])
                            : __ldg(&U[(size_t)k * 512 + n]);
        #pragma unroll
        for (int j = 0; j < 16; ++j)
            s[j] += Ts[(jg * 16 + j) * 64 + k] * w;
    }
    const float sc = mat ? 1.0f : g_sigma[n];
    float* dst = mat ? g_Wvp : g_C1;
    #pragma unroll
    for (int j = 0; j < 16; ++j)
        dst[(size_t)(jg * 16 + j) * 512 + n] = s[j] * sc;
}

// ---------------------------------------------------------------------------
// c2k: C2[a][b] = sum_j C1[a][j] * Wv~[b][j].  Warp per entry.
// ---------------------------------------------------------------------------
__global__ __launch_bounds__(256)
void c2_kernel(const float* __restrict__ V)
{
    const int task = blockIdx.x * 8 + (threadIdx.x >> 5);  // 0..4095
    const int lane = threadIdx.x & 31;
    const int a = task >> 6, b = task & 63;
    const float* c1 = g_C1 + (size_t)a * 512;
    const float* vv = V + (size_t)(63 - b) * 512;
    float ss = 0.f;
    #pragma unroll
    for (int j = lane; j < 512; j += 32) ss += c1[j] * vv[j];
    #pragma unroll
    for (int o = 16; o > 0; o >>= 1) ss += __shfl_xor_sync(0xffffffffu, ss, o);
    if (lane == 0) g_C2[a * 64 + b] = ss;
}

// ---------------------------------------------------------------------------
// ek: E[i][b] = sigma_i * Wv~[b][i] - sum_a U[a][i] * C2[a][b]
// ---------------------------------------------------------------------------
__global__ __launch_bounds__(256)
void e_kernel(const float* __restrict__ U, const float* __restrict__ V)
{
    __shared__ float c2s[64];
    const int b = blockIdx.x >> 1;
    const int i = (blockIdx.x & 1) * 256 + threadIdx.x;
    if (threadIdx.x < 64) c2s[threadIdx.x] = g_C2[threadIdx.x * 64 + b];
    __syncthreads();
    float s = g_sigma[i] * __ldg(&V[(size_t)(63 - b) * 512 + i]);
    #pragma unroll 8
    for (int a = 0; a < 64; ++a)
        s -= __ldg(&U[(size_t)a * 512 + i]) * c2s[a];
    g_E[(size_t)i * 64 + b] = s;
}

// ---------------------------------------------------------------------------
// buildM: M[i][j] = sigma_i*d_ij - sum_a U[a][i]*C1[a][j] - sum_b E[i][b]*Wvp[b][j]
// Tile 64x64 per block, grid (8,8). Writes M^T fp16.
// ---------------------------------------------------------------------------
#define BM_SMEM 65536
__global__ __launch_bounds__(256)
void buildM_kernel(const float* __restrict__ U)
{
    extern __shared__ float s4[];
    float* Us  = s4;             // [a][di]
    float* C1s = s4 + 4096;      // [a][dj]
    float* EsT = s4 + 8192;      // [b][di]
    float* Ws  = s4 + 12288;     // [b][dj]
    const int t = threadIdx.x;
    const int i0 = blockIdx.x * 64, j0 = blockIdx.y * 64;

    for (int idx = t; idx < 4096; idx += 256) {
        const int a = idx >> 6, d = idx & 63;
        Us[idx]  = __ldg(&U[(size_t)a * 512 + i0 + d]);
        C1s[idx] = g_C1[(size_t)a * 512 + j0 + d];
        EsT[idx] = g_E[(size_t)(i0 + d) * 64 + a];   // transpose on load
        Ws[idx]  = g_Wvp[(size_t)a * 512 + j0 + d];
    }
    __syncthreads();

    const int ti = t & 15, tj = t >> 4;
    float acc[4][4];
    #pragma unroll
    for (int r = 0; r < 4; ++r)
        #pragma unroll
        for (int c = 0; c < 4; ++c) acc[r][c] = 0.f;

    #pragma unroll 4
    for (int a = 0; a < 64; ++a) {
        float ua[4], c1[4];
        #pragma unroll
        for (int r = 0; r < 4; ++r) ua[r] = Us[a * 64 + ti * 4 + r];
        #pragma unroll
        for (int c = 0; c < 4; ++c) c1[c] = C1s[a * 64 + tj * 4 + c];
        #pragma unroll
        for (int r = 0; r < 4; ++r)
            #pragma unroll
            for (int c = 0; c < 4; ++c) acc[r][c] -= ua[r] * c1[c];
    }
    #pragma unroll 4
    for (int b = 0; b < 64; ++b) {
        float e[4], wv[4];
        #pragma unroll
        for (int r = 0; r < 4; ++r) e[r] = EsT[b * 64 + ti * 4 + r];
        #pragma unroll
        for (int c = 0; c < 4; ++c) wv[c] = Ws[b * 64 + tj * 4 + c];
        #pragma unroll
        for (int r = 0; r < 4; ++r)
            #pragma unroll
            for (int c = 0; c < 4; ++c) acc[r][c] -= e[r] * wv[c];
    }

    #pragma unroll
    for (int r = 0; r < 4; ++r) {
        const int i = i0 + ti * 4 + r;
        #pragma unroll
        for (int c = 0; c < 4; ++c) {
            const int j = j0 + tj * 4 + c;
            float m = acc[r][c] + (i == j ? g_sigma[i] : 0.f);
            g_MT[(size_t)j * 512 + i] = __float2half_rn(m);
        }
    }
}

// ---------------------------------------------------------------------------
// GEMM (R9-validated): out = x_h * M^T^T + bias, K=512, CTA 128x128, 3 stages.
// ---------------------------------------------------------------------------
#define TM 128
#define TN 128
#define NKS 16
#define STG 16384

__global__ __launch_bounds__(256, 2)
void gemm_kernel(float* __restrict__ out, const float* __restrict__ bias)
{
    __shared__ __align__(1024) uint8_t smem[3 * STG];
    const uint32_t sbase = smem_u32(smem);
    const int t = threadIdx.x;
    const int lane = t & 31, wid = t >> 5;
    const int wm = wid & 3, wn = wid >> 2;
    const int m0 = blockIdx.x * TM, n0 = blockIdx.y * TN;

    float acc[2][8][4];
    #pragma unroll
    for (int fm = 0; fm < 2; ++fm)
        #pragma unroll
        for (int fn = 0; fn < 8; ++fn)
            #pragma unroll
            for (int j = 0; j < 4; ++j) acc[fm][fn][j] = 0.f;

    auto load_stage = [&](int st, int ks) {
        const __half* Ab = g_xh + (size_t)m0 * 512 + ks * 32;
        const __half* Bb = (const __half*)g_MT + (size_t)n0 * 512 + ks * 32;
        const uint32_t sA = sbase + st * STG;
        const uint32_t sB = sA + 8192;
        #pragma unroll
        for (int i = 0; i < 2; ++i) {
            const int idx = t + i * 256;
            const int row = idx >> 2, c = idx & 3;
            cp_async16(sA + SWZ64((uint32_t)(row * 64 + c * 16)),
                       Ab + (size_t)row * 512 + c * 8);
        }
        #pragma unroll
        for (int i = 0; i < 2; ++i) {
            const int idx = t + i * 256;
            const int row = idx >> 2, c = idx & 3;
            cp_async16(sB + SWZ64((uint32_t)(row * 64 + c * 16)),
                       Bb + (size_t)row * 512 + c * 8);
        }
    };

    auto compute_stage = [&](int st) {
        const uint32_t sA = sbase + st * STG;
        const uint32_t sB = sA + 8192;
        #pragma unroll
        for (int kf = 0; kf < 2; ++kf) {
            uint32_t a[2][4], b[4][4];
            #pragma unroll
            for (int fm = 0; fm < 2; ++fm) {
                const int row = wm * 32 + fm * 16 + (lane & 15);
                const int c   = kf * 2 + (lane >> 4);
                ldsm_x4(a[fm], sA + SWZ64((uint32_t)(row * 64 + c * 16)));
            }
            #pragma unroll
            for (int fp = 0; fp < 4; ++fp) {
                const int row = wn * 64 + fp * 16 + ((lane >> 4) << 3) + (lane & 7);
                const int c   = kf * 2 + ((lane >> 3) & 1);
                ldsm_x4(b[fp], sB + SWZ64((uint32_t)(row * 64 + c * 16)));
            }
            #pragma unroll
            for (int fm = 0; fm < 2; ++fm)
                #pragma unroll
                for (int fn = 0; fn < 8; ++fn)
                    mma16816(acc[fm][fn], a[fm], &b[fn >> 1][(fn & 1) * 2]);
        }
    };

    load_stage(0, 0); CP_COMMIT();
    load_stage(1, 1); CP_COMMIT();

    #pragma unroll 1
    for (int ks = 0; ks < NKS; ++ks) {
        CP_WAIT1();
        __syncthreads();
        const int kn = ks + 2;
        if (kn < NKS) load_stage(kn % 3, kn);
        CP_COMMIT();
        compute_stage(ks % 3);
    }

    #pragma unroll
    for (int fm = 0; fm < 2; ++fm) {
        const int r = m0 + wm * 32 + fm * 16 + (lane >> 2);
        #pragma unroll
        for (int fn = 0; fn < 8; ++fn) {
            const int cb = n0 + wn * 64 + fn * 8 + (lane & 3) * 2;
            const float2 bi = __ldg((const float2*)(bias + cb));
            float2 v0, v1;
            v0.x = acc[fm][fn][0] + bi.x; v0.y = acc[fm][fn][1] + bi.y;
            v1.x = acc[fm][fn][2] + bi.x; v1.y = acc[fm][fn][3] + bi.y;
            *(float2*)(out + (size_t)r * 512 + cb)       = v0;
            *(float2*)(out + (size_t)(r + 8) * 512 + cb) = v1;
        }
    }
}

// ---------------------------------------------------------------------------
extern "C" void kernel_launch(void* const* d_in, const int* in_sizes, int n_in,
                              void* d_out, int out_size)
{
    (void)in_sizes; (void)n_in; (void)out_size;
    const float* x    = (const float*)d_in[0];
    const float* p    = (const float*)d_in[1];
    const float* U    = (const float*)d_in[2];
    const float* V    = (const float*)d_in[3];
    const float* bias = (const float*)d_in[4];

    cudaFuncSetAttribute(buildM_kernel, cudaFuncAttributeMaxDynamicSharedMemorySize,
                         BM_SMEM);

    k1_kernel<<<4096 + 1024, 256>>>((const float4*)x, U, V);
    tinv_kernel<<<4, 1024>>>(p);
    applyT_kernel<<<16, 256>>>(U, V);
    c2_kernel<<<512, 256>>>(V);
    e_kernel<<<128, 256>>>(U, V);
    buildM_kernel<<<dim3(8, 8), 256, BM_SMEM>>>(U);
    gemm_kernel<<<dim3(BATCH / TM, 512 / TN), 256>>>((float*)d_out, bias);
}